// round 1
// baseline (speedup 1.0000x reference)
#include <cuda_runtime.h>

#define HIDSZ 256
#define NAGENTS 8
#define NMODELS 64
#define NACTIONS 16
#define BN 256
#define IN_DIM 512
#define COMM_OUT (HIDSZ * NAGENTS)   // 2048

// Output layout (concatenated in reference return order, fp32):
#define OFF_ACT  0
#define OFF_BASE (BN * NACTIONS)          // 4096
#define OFF_HID  (OFF_BASE + BN)          // 4352
#define OFF_COMM (OFF_HID + BN * HIDSZ)   // 69888
// total = 594176

// ---------------- grouping scratch (device globals; no allocation) ----------
__device__ int   g_rows[BN];                 // row indices, sorted by model
__device__ int   g_nchunks4;
__device__ int   g_nchunks8;
__device__ short g_c4_m[160], g_c4_s[160], g_c4_n[160];
__device__ short g_c8_m[160], g_c8_s[160], g_c8_n[160];

// ---------------------------------------------------------------------------
// Kernel 0: group rows by model id, build chunk worklists.
// ---------------------------------------------------------------------------
__global__ void group_kernel(const int* __restrict__ ids) {
    __shared__ int cnt[NMODELS];
    __shared__ int off[NMODELS + 1];
    __shared__ int cur[NMODELS];
    int t = threadIdx.x;
    if (t < NMODELS) cnt[t] = 0;
    __syncthreads();
    int m = ids[t];
    atomicAdd(&cnt[m], 1);
    __syncthreads();
    if (t == 0) {
        int a = 0;
        for (int i = 0; i < NMODELS; i++) { off[i] = a; a += cnt[i]; }
        off[NMODELS] = a;
    }
    __syncthreads();
    if (t < NMODELS) cur[t] = off[t];
    __syncthreads();
    int pos = atomicAdd(&cur[m], 1);
    g_rows[pos] = t;
    __syncthreads();
    if (t == 0) {
        int n4 = 0, n8 = 0;
        for (int i = 0; i < NMODELS; i++) {
            int s = off[i], n = cnt[i];
            for (int c = 0; c < n; c += 4) {
                g_c4_m[n4] = (short)i; g_c4_s[n4] = (short)(s + c);
                g_c4_n[n4] = (short)min(4, n - c); n4++;
            }
            for (int c = 0; c < n; c += 8) {
                g_c8_m[n8] = (short)i; g_c8_s[n8] = (short)(s + c);
                g_c8_n[n8] = (short)min(8, n - c); n8++;
            }
        }
        g_nchunks4 = n4;
        g_nchunks8 = n8;
    }
}

// ---------------------------------------------------------------------------
// Kernel 1: hid = relu(inp@enc_w + enc_b + prev_hid@rnn_w[m] + rnn_b[m] + sum_a comm_in)
// Grid: (128 chunk slots, 2 col-halves), block 128. R=4 rows per chunk.
// ---------------------------------------------------------------------------
__global__ void hid_kernel(const float* __restrict__ inp,
                           const float* __restrict__ prev,
                           const float* __restrict__ comm_in,
                           const float* __restrict__ enc_w,
                           const float* __restrict__ enc_b,
                           const float* __restrict__ rnn_w,
                           const float* __restrict__ rnn_b,
                           float* __restrict__ out) {
    int ci = blockIdx.x;
    if (ci >= g_nchunks4) return;
    const int m = g_c4_m[ci];
    const int s = g_c4_s[ci];
    const int n = g_c4_n[ci];
    const int j = blockIdx.y * 128 + threadIdx.x;

    __shared__ float sh_in[4][IN_DIM];
    __shared__ float sh_ph[4][HIDSZ];
    __shared__ int   rows[4];
    if (threadIdx.x < n) rows[threadIdx.x] = g_rows[s + threadIdx.x];
    __syncthreads();

    for (int r = 0; r < 4; r++) {
        if (r < n) {
            int row = rows[r];
            for (int k = threadIdx.x; k < IN_DIM; k += 128) sh_in[r][k] = inp[row * IN_DIM + k];
            for (int k = threadIdx.x; k < HIDSZ;  k += 128) sh_ph[r][k] = prev[row * HIDSZ + k];
        } else {
            for (int k = threadIdx.x; k < IN_DIM; k += 128) sh_in[r][k] = 0.f;
            for (int k = threadIdx.x; k < HIDSZ;  k += 128) sh_ph[r][k] = 0.f;
        }
    }
    __syncthreads();

    float acc[4];
    const float eb = enc_b[j];
    const float rb = rnn_b[m * HIDSZ + j];
    #pragma unroll
    for (int r = 0; r < 4; r++) acc[r] = eb + rb;
    for (int r = 0; r < n; r++) {
        const float* cb = comm_in + (size_t)rows[r] * NAGENTS * HIDSZ + j;
        float c = 0.f;
        #pragma unroll
        for (int a = 0; a < NAGENTS; a++) c += cb[a * HIDSZ];
        acc[r] += c;
    }

    // enc part (shared weights)
    {
        const float* w = enc_w + j;
        #pragma unroll 4
        for (int k = 0; k < IN_DIM; k++) {
            float wv = w[(size_t)k * HIDSZ];
            #pragma unroll
            for (int r = 0; r < 4; r++) acc[r] += sh_in[r][k] * wv;
        }
    }
    // rnn part (model-gathered weights)
    {
        const float* w = rnn_w + (size_t)m * HIDSZ * HIDSZ + j;
        #pragma unroll 4
        for (int k = 0; k < HIDSZ; k++) {
            float wv = w[(size_t)k * HIDSZ];
            #pragma unroll
            for (int r = 0; r < 4; r++) acc[r] += sh_ph[r][k] * wv;
        }
    }
    for (int r = 0; r < n; r++)
        out[OFF_HID + (size_t)rows[r] * HIDSZ + j] = fmaxf(acc[r], 0.f);
}

// ---------------------------------------------------------------------------
// Kernel 2: comm_out = hid @ comm_w[m] + comm_b[m].  R=8 rows per chunk.
// Grid: (96 chunk slots, 16 col-tiles of 128), block 128.
// ---------------------------------------------------------------------------
__global__ void comm_kernel(const float* __restrict__ comm_w,
                            const float* __restrict__ comm_b,
                            float* __restrict__ out) {
    int ci = blockIdx.x;
    if (ci >= g_nchunks8) return;
    const int m = g_c8_m[ci];
    const int s = g_c8_s[ci];
    const int n = g_c8_n[ci];
    const int j = blockIdx.y * 128 + threadIdx.x;

    __shared__ float sh_h[8][HIDSZ];
    __shared__ int   rows[8];
    if (threadIdx.x < n) rows[threadIdx.x] = g_rows[s + threadIdx.x];
    __syncthreads();

    const float* hid = out + OFF_HID;
    for (int r = 0; r < 8; r++) {
        if (r < n) {
            int row = rows[r];
            for (int k = threadIdx.x; k < HIDSZ; k += 128) sh_h[r][k] = hid[(size_t)row * HIDSZ + k];
        } else {
            for (int k = threadIdx.x; k < HIDSZ; k += 128) sh_h[r][k] = 0.f;
        }
    }
    __syncthreads();

    float acc[8];
    const float b = comm_b[(size_t)m * COMM_OUT + j];
    #pragma unroll
    for (int r = 0; r < 8; r++) acc[r] = b;

    const float* w = comm_w + (size_t)m * HIDSZ * COMM_OUT + j;
    #pragma unroll 4
    for (int k = 0; k < HIDSZ; k++) {
        float wv = w[(size_t)k * COMM_OUT];
        #pragma unroll
        for (int r = 0; r < 8; r++) acc[r] += sh_h[r][k] * wv;
    }
    for (int r = 0; r < n; r++)
        out[OFF_COMM + (size_t)rows[r] * COMM_OUT + j] = acc[r];
}

// ---------------------------------------------------------------------------
// Kernel 3: action_prob = softmax(hid @ act_w[m] + act_b[m]); baseline.
// One warp per row.
// ---------------------------------------------------------------------------
__global__ void act_kernel(const int* __restrict__ ids,
                           const float* __restrict__ act_w,
                           const float* __restrict__ act_b,
                           const float* __restrict__ base_w,
                           const float* __restrict__ base_b,
                           float* __restrict__ out) {
    const int b = blockIdx.x;
    const int m = ids[b];
    const int lane = threadIdx.x;
    __shared__ float sh[HIDSZ];
    __shared__ float logits[NACTIONS];

    for (int k = lane; k < HIDSZ; k += 32) sh[k] = out[OFF_HID + (size_t)b * HIDSZ + k];
    __syncwarp();

    if (lane < NACTIONS) {
        const float* w = act_w + (size_t)m * HIDSZ * NACTIONS + lane;
        float a = act_b[m * NACTIONS + lane];
        #pragma unroll 8
        for (int k = 0; k < HIDSZ; k++) a += sh[k] * w[(size_t)k * NACTIONS];
        logits[lane] = a;
    } else if (lane == 16) {
        const float* w = base_w + (size_t)m * HIDSZ;
        float a = base_b[m];
        #pragma unroll 8
        for (int k = 0; k < HIDSZ; k++) a += sh[k] * w[k];
        out[OFF_BASE + b] = a;
    }
    __syncwarp();

    if (lane < NACTIONS) {
        float x = logits[lane];
        float mx = x;
        #pragma unroll
        for (int o = 8; o > 0; o >>= 1) mx = fmaxf(mx, __shfl_xor_sync(0x0000ffffu, mx, o, 16));
        float e = expf(x - mx);
        float ssum = e;
        #pragma unroll
        for (int o = 8; o > 0; o >>= 1) ssum += __shfl_xor_sync(0x0000ffffu, ssum, o, 16);
        out[OFF_ACT + (size_t)b * NACTIONS + lane] = e / ssum;
    }
}

// ---------------------------------------------------------------------------
extern "C" void kernel_launch(void* const* d_in, const int* in_sizes, int n_in,
                              void* d_out, int out_size) {
    const float* inp      = (const float*)d_in[0];   // [256, 512]
    const float* prev_hid = (const float*)d_in[1];   // [256, 256]
    const float* comm_in  = (const float*)d_in[2];   // [256, 8, 256]
    const int*   ids      = (const int*)  d_in[3];   // [256]
    const float* enc_w    = (const float*)d_in[4];   // [512, 256]
    const float* enc_b    = (const float*)d_in[5];   // [256]
    const float* rnn_w    = (const float*)d_in[6];   // [64, 256, 256]
    const float* rnn_b    = (const float*)d_in[7];   // [64, 256]
    const float* act_w    = (const float*)d_in[8];   // [64, 256, 16]
    const float* act_b    = (const float*)d_in[9];   // [64, 16]
    const float* base_w   = (const float*)d_in[10];  // [64, 256, 1]
    const float* base_b   = (const float*)d_in[11];  // [64, 1]
    const float* comm_w   = (const float*)d_in[12];  // [64, 256, 2048]
    const float* comm_b   = (const float*)d_in[13];  // [64, 2048]
    float* out = (float*)d_out;

    group_kernel<<<1, BN>>>(ids);
    hid_kernel<<<dim3(128, 2), 128>>>(inp, prev_hid, comm_in,
                                      enc_w, enc_b, rnn_w, rnn_b, out);
    comm_kernel<<<dim3(96, 16), 128>>>(comm_w, comm_b, out);
    act_kernel<<<BN, 32>>>(ids, act_w, act_b, base_w, base_b, out);
}

// round 2
// speedup vs baseline: 2.1185x; 2.1185x over previous
#include <cuda_runtime.h>

#define HIDSZ 256
#define NAGENTS 8
#define NMODELS 64
#define NACTIONS 16
#define BN 256
#define IN_DIM 512
#define COMM_OUT (HIDSZ * NAGENTS)   // 2048

// Output layout (concatenated in reference return order, fp32):
#define OFF_ACT  0
#define OFF_BASE (BN * NACTIONS)          // 4096
#define OFF_HID  (OFF_BASE + BN)          // 4352
#define OFF_COMM (OFF_HID + BN * HIDSZ)   // 69888
// total = 594176

// ---------------- grouping scratch (device globals; no allocation) ----------
__device__ int   g_rows[BN];      // row indices, sorted by model
__device__ int   g_nchunks8;
__device__ short g_c8_m[128], g_c8_s[128], g_c8_n[128];

// ---------------------------------------------------------------------------
// Kernel 0: group rows by model id, build 8-row chunk worklist for comm GEMM.
// ---------------------------------------------------------------------------
__global__ void group_kernel(const int* __restrict__ ids) {
    __shared__ int cnt[NMODELS];
    __shared__ int off[NMODELS + 1];
    __shared__ int cur[NMODELS];
    int t = threadIdx.x;
    if (t < NMODELS) cnt[t] = 0;
    __syncthreads();
    int m = ids[t];
    atomicAdd(&cnt[m], 1);
    __syncthreads();
    if (t == 0) {
        int a = 0;
        for (int i = 0; i < NMODELS; i++) { off[i] = a; a += cnt[i]; }
        off[NMODELS] = a;
    }
    __syncthreads();
    if (t < NMODELS) cur[t] = off[t];
    __syncthreads();
    int pos = atomicAdd(&cur[m], 1);
    g_rows[pos] = t;
    if (t == 0) {
        int n8 = 0;
        for (int i = 0; i < NMODELS; i++) {
            int s = off[i], n = cnt[i];
            for (int c = 0; c < n; c += 8) {
                g_c8_m[n8] = (short)i; g_c8_s[n8] = (short)(s + c);
                g_c8_n[n8] = (short)min(8, n - c); n8++;
            }
        }
        g_nchunks8 = n8;
    }
}

// ---------------------------------------------------------------------------
// Kernel 1 (fused): per-row hid = relu(enc + rnn + comm_sum), then
// action softmax + baseline for the same row, all in one 256-thread block.
// ---------------------------------------------------------------------------
__global__ void __launch_bounds__(256)
hid_act_kernel(const float* __restrict__ inp,
               const float* __restrict__ prev,
               const float* __restrict__ comm_in,
               const int*   __restrict__ ids,
               const float* __restrict__ enc_w,
               const float* __restrict__ enc_b,
               const float* __restrict__ rnn_w,
               const float* __restrict__ rnn_b,
               const float* __restrict__ act_w,
               const float* __restrict__ act_b,
               const float* __restrict__ base_w,
               const float* __restrict__ base_b,
               float* __restrict__ out) {
    const int b = blockIdx.x;
    const int j = threadIdx.x;

    __shared__ float sx[IN_DIM];     // input row
    __shared__ float sp[HIDSZ];      // prev_hid row
    __shared__ float sh[HIDSZ];      // hid row
    __shared__ float part[256];      // act partials [o*16 + s]
    __shared__ float bpart[8];       // baseline per-warp partials

    if (j < 128)      ((float4*)sx)[j] = ((const float4*)(inp  + (size_t)b * IN_DIM))[j];
    else if (j < 192) ((float4*)sp)[j - 128] = ((const float4*)(prev + (size_t)b * HIDSZ))[j - 128];
    const int m = ids[b];
    __syncthreads();

    // comm sum over incoming agents
    float c = 0.f;
    {
        const float* cb = comm_in + (size_t)b * NAGENTS * HIDSZ + j;
        #pragma unroll
        for (int a = 0; a < NAGENTS; a++) c += cb[a * HIDSZ];
    }

    float a0 = enc_b[j] + rnn_b[m * HIDSZ + j] + c;
    float a1 = 0.f, a2 = 0.f, a3 = 0.f;

    // enc: inp @ enc_w (shared weights)
    {
        const float* w = enc_w + j;
        #pragma unroll 4
        for (int k = 0; k < IN_DIM; k += 4) {
            a0 += sx[k + 0] * w[(k + 0) * HIDSZ];
            a1 += sx[k + 1] * w[(k + 1) * HIDSZ];
            a2 += sx[k + 2] * w[(k + 2) * HIDSZ];
            a3 += sx[k + 3] * w[(k + 3) * HIDSZ];
        }
    }
    // rnn: prev_hid @ rnn_w[m]
    {
        const float* w = rnn_w + (size_t)m * HIDSZ * HIDSZ + j;
        #pragma unroll 4
        for (int k = 0; k < HIDSZ; k += 4) {
            a0 += sp[k + 0] * w[(k + 0) * HIDSZ];
            a1 += sp[k + 1] * w[(k + 1) * HIDSZ];
            a2 += sp[k + 2] * w[(k + 2) * HIDSZ];
            a3 += sp[k + 3] * w[(k + 3) * HIDSZ];
        }
    }
    float h = fmaxf((a0 + a1) + (a2 + a3), 0.f);
    sh[j] = h;
    out[OFF_HID + (size_t)b * HIDSZ + j] = h;

    // baseline partial (per-thread, warp-reduced)
    float bp = h * base_w[(size_t)m * HIDSZ + j];
    #pragma unroll
    for (int o = 16; o > 0; o >>= 1) bp += __shfl_xor_sync(0xffffffffu, bp, o);
    if ((j & 31) == 0) bpart[j >> 5] = bp;
    __syncthreads();

    // action partials: output o = j&15, k-slice s = j>>4 (16 k's each)
    {
        const int o = j & 15, s = j >> 4;
        const float* aw = act_w + (size_t)m * HIDSZ * NACTIONS + o;
        float p = 0.f;
        #pragma unroll
        for (int kk = 0; kk < 16; kk++) {
            int k = s * 16 + kk;
            p += sh[k] * aw[(size_t)k * NACTIONS];
        }
        part[o * 16 + s] = p;
    }
    __syncthreads();

    if (j < NACTIONS) {
        float l = act_b[m * NACTIONS + j];
        #pragma unroll
        for (int s = 0; s < 16; s++) l += part[j * 16 + s];
        float mx = l;
        #pragma unroll
        for (int o = 8; o > 0; o >>= 1) mx = fmaxf(mx, __shfl_xor_sync(0x0000ffffu, mx, o, 16));
        float e = expf(l - mx);
        float ssum = e;
        #pragma unroll
        for (int o = 8; o > 0; o >>= 1) ssum += __shfl_xor_sync(0x0000ffffu, ssum, o, 16);
        out[OFF_ACT + (size_t)b * NACTIONS + j] = e / ssum;
    } else if (j == 16) {
        float v = base_b[m];
        #pragma unroll
        for (int w8 = 0; w8 < 8; w8++) v += bpart[w8];
        out[OFF_BASE + b] = v;
    }
}

// ---------------------------------------------------------------------------
// Kernel 2: comm_out = hid @ comm_w[m] + comm_b[m].  R=8 rows per chunk,
// float4 shared reads, 4-wide weight-load batches for MLP.
// ---------------------------------------------------------------------------
__global__ void __launch_bounds__(128)
comm_kernel(const float* __restrict__ comm_w,
            const float* __restrict__ comm_b,
            float* __restrict__ out) {
    int ci = blockIdx.x;
    if (ci >= g_nchunks8) return;
    const int m = g_c8_m[ci];
    const int s = g_c8_s[ci];
    const int n = g_c8_n[ci];
    const int j = blockIdx.y * 128 + threadIdx.x;

    __shared__ float4 sh[8][HIDSZ / 4];
    __shared__ int    rows[8];
    if (threadIdx.x < 8)
        rows[threadIdx.x] = (threadIdx.x < n) ? g_rows[s + threadIdx.x] : -1;
    __syncthreads();

    const float* hid = out + OFF_HID;
    for (int idx = threadIdx.x; idx < 8 * (HIDSZ / 4); idx += 128) {
        int r = idx >> 6, k = idx & 63;
        sh[r][k] = (rows[r] >= 0)
                       ? ((const float4*)(hid + (size_t)rows[r] * HIDSZ))[k]
                       : make_float4(0.f, 0.f, 0.f, 0.f);
    }
    __syncthreads();

    float acc[8];
    const float bias = comm_b[(size_t)m * COMM_OUT + j];
    #pragma unroll
    for (int r = 0; r < 8; r++) acc[r] = bias;

    const float* w = comm_w + (size_t)m * HIDSZ * COMM_OUT + j;
    #pragma unroll 2
    for (int kq = 0; kq < HIDSZ / 4; kq++) {
        float w0 = w[(size_t)(4 * kq + 0) * COMM_OUT];
        float w1 = w[(size_t)(4 * kq + 1) * COMM_OUT];
        float w2 = w[(size_t)(4 * kq + 2) * COMM_OUT];
        float w3 = w[(size_t)(4 * kq + 3) * COMM_OUT];
        #pragma unroll
        for (int r = 0; r < 8; r++) {
            float4 h = sh[r][kq];
            acc[r] += h.x * w0 + h.y * w1 + h.z * w2 + h.w * w3;
        }
    }
    for (int r = 0; r < n; r++)
        out[OFF_COMM + (size_t)rows[r] * COMM_OUT + j] = acc[r];
}

// ---------------------------------------------------------------------------
extern "C" void kernel_launch(void* const* d_in, const int* in_sizes, int n_in,
                              void* d_out, int out_size) {
    const float* inp      = (const float*)d_in[0];   // [256, 512]
    const float* prev_hid = (const float*)d_in[1];   // [256, 256]
    const float* comm_in  = (const float*)d_in[2];   // [256, 8, 256]
    const int*   ids      = (const int*)  d_in[3];   // [256]
    const float* enc_w    = (const float*)d_in[4];   // [512, 256]
    const float* enc_b    = (const float*)d_in[5];   // [256]
    const float* rnn_w    = (const float*)d_in[6];   // [64, 256, 256]
    const float* rnn_b    = (const float*)d_in[7];   // [64, 256]
    const float* act_w    = (const float*)d_in[8];   // [64, 256, 16]
    const float* act_b    = (const float*)d_in[9];   // [64, 16]
    const float* base_w   = (const float*)d_in[10];  // [64, 256, 1]
    const float* base_b   = (const float*)d_in[11];  // [64, 1]
    const float* comm_w   = (const float*)d_in[12];  // [64, 256, 2048]
    const float* comm_b   = (const float*)d_in[13];  // [64, 2048]
    float* out = (float*)d_out;

    group_kernel<<<1, BN>>>(ids);
    hid_act_kernel<<<BN, 256>>>(inp, prev_hid, comm_in, ids,
                                enc_w, enc_b, rnn_w, rnn_b,
                                act_w, act_b, base_w, base_b, out);
    comm_kernel<<<dim3(96, 16), 128>>>(comm_w, comm_b, out);
}

// round 3
// speedup vs baseline: 2.1587x; 1.0190x over previous
#include <cuda_runtime.h>

#define HIDSZ 256
#define NAGENTS 8
#define NMODELS 64
#define NACTIONS 16
#define BN 256
#define IN_DIM 512
#define COMM_OUT (HIDSZ * NAGENTS)   // 2048

// Output layout (concatenated in reference return order, fp32):
#define OFF_ACT  0
#define OFF_BASE (BN * NACTIONS)          // 4096
#define OFF_HID  (OFF_BASE + BN)          // 4352
#define OFF_COMM (OFF_HID + BN * HIDSZ)   // 69888

// ---------------- grouping scratch (device globals; no allocation) ----------
__device__ int g_rows[BN];      // row indices, sorted by model
__device__ int g_nchunks;
__device__ int g_cm[BN], g_cs[BN], g_cn[BN];   // chunk: model, start, count

// ---------------------------------------------------------------------------
// Kernel 0: group rows by model id, build chunk worklist (parallel scans).
// ---------------------------------------------------------------------------
__global__ void group_kernel(const int* __restrict__ ids) {
    __shared__ int cnt[NMODELS];
    __shared__ int off[NMODELS];
    __shared__ int coff[NMODELS];
    __shared__ int cur[NMODELS];
    __shared__ int tmp[NMODELS];
    const int t = threadIdx.x;

    if (t < NMODELS) cnt[t] = 0;
    __syncthreads();
    const int m = ids[t];
    atomicAdd(&cnt[m], 1);
    __syncthreads();

    // exclusive scan of cnt -> off, and of chunk counts -> coff (Hillis-Steele)
    if (t < NMODELS) {
        off[t] = cnt[t];
        coff[t] = (cnt[t] + 7) >> 3;
    }
    __syncthreads();
    #pragma unroll
    for (int d = 1; d < NMODELS; d <<= 1) {
        int a = 0, b = 0;
        if (t < NMODELS && t >= d) { a = off[t - d]; b = coff[t - d]; }
        __syncthreads();
        if (t < NMODELS && t >= d) { off[t] += a; coff[t] += b; }
        __syncthreads();
    }
    // convert inclusive -> exclusive
    if (t < NMODELS) {
        tmp[t] = off[t] - cnt[t];                 // exclusive row offset
        cur[t] = tmp[t];
        if (t == NMODELS - 1) g_nchunks = coff[t];
    }
    __syncthreads();
    if (t < NMODELS) {
        int co = coff[t] - ((cnt[t] + 7) >> 3);   // exclusive chunk offset
        int s = tmp[t], n = cnt[t];
        for (int c = 0; c < n; c += 8) {
            g_cm[co] = t;
            g_cs[co] = s + c;
            g_cn[co] = min(8, n - c);
            co++;
        }
    }
    __syncthreads();
    int pos = atomicAdd(&cur[m], 1);
    g_rows[pos] = t;
}

// ---------------------------------------------------------------------------
// Kernel 1 (fused): per-row hid = relu(enc + rnn + comm_sum), then
// action softmax + baseline for the same row, one 256-thread block per row.
// ---------------------------------------------------------------------------
__global__ void __launch_bounds__(256)
hid_act_kernel(const float* __restrict__ inp,
               const float* __restrict__ prev,
               const float* __restrict__ comm_in,
               const int*   __restrict__ ids,
               const float* __restrict__ enc_w,
               const float* __restrict__ enc_b,
               const float* __restrict__ rnn_w,
               const float* __restrict__ rnn_b,
               const float* __restrict__ act_w,
               const float* __restrict__ act_b,
               const float* __restrict__ base_w,
               const float* __restrict__ base_b,
               float* __restrict__ out) {
    const int b = blockIdx.x;
    const int j = threadIdx.x;

    __shared__ float sx[IN_DIM];     // input row
    __shared__ float sp[HIDSZ];      // prev_hid row
    __shared__ float sh[HIDSZ];      // hid row
    __shared__ float part[256];      // act partials [o*16 + s]
    __shared__ float bpart[8];       // baseline per-warp partials

    if (j < 128)      ((float4*)sx)[j] = ((const float4*)(inp  + (size_t)b * IN_DIM))[j];
    else if (j < 192) ((float4*)sp)[j - 128] = ((const float4*)(prev + (size_t)b * HIDSZ))[j - 128];
    const int m = ids[b];
    __syncthreads();

    // comm sum over incoming agents
    float c = 0.f;
    {
        const float* cb = comm_in + (size_t)b * NAGENTS * HIDSZ + j;
        #pragma unroll
        for (int a = 0; a < NAGENTS; a++) c += cb[a * HIDSZ];
    }

    float acc[8];
    acc[0] = enc_b[j] + rnn_b[m * HIDSZ + j] + c;
    #pragma unroll
    for (int r = 1; r < 8; r++) acc[r] = 0.f;

    // enc: inp @ enc_w (shared weights), 8-wide load batches
    {
        const float* w = enc_w + j;
        #pragma unroll 2
        for (int k = 0; k < IN_DIM; k += 8) {
            #pragma unroll
            for (int u = 0; u < 8; u++)
                acc[u] += sx[k + u] * w[(k + u) * HIDSZ];
        }
    }
    // rnn: prev_hid @ rnn_w[m]
    {
        const float* w = rnn_w + (size_t)m * HIDSZ * HIDSZ + j;
        #pragma unroll 2
        for (int k = 0; k < HIDSZ; k += 8) {
            #pragma unroll
            for (int u = 0; u < 8; u++)
                acc[u] += sp[k + u] * w[(k + u) * HIDSZ];
        }
    }
    float h = ((acc[0] + acc[1]) + (acc[2] + acc[3])) +
              ((acc[4] + acc[5]) + (acc[6] + acc[7]));
    h = fmaxf(h, 0.f);
    sh[j] = h;
    out[OFF_HID + (size_t)b * HIDSZ + j] = h;

    // baseline partial (per-thread, warp-reduced)
    float bp = h * base_w[(size_t)m * HIDSZ + j];
    #pragma unroll
    for (int o = 16; o > 0; o >>= 1) bp += __shfl_xor_sync(0xffffffffu, bp, o);
    if ((j & 31) == 0) bpart[j >> 5] = bp;
    __syncthreads();

    // action partials: output o = j&15, k-slice s = j>>4 (16 k's each)
    {
        const int o = j & 15, s = j >> 4;
        const float* aw = act_w + (size_t)m * HIDSZ * NACTIONS + o;
        float p = 0.f;
        #pragma unroll
        for (int kk = 0; kk < 16; kk++) {
            int k = s * 16 + kk;
            p += sh[k] * aw[(size_t)k * NACTIONS];
        }
        part[o * 16 + s] = p;
    }
    __syncthreads();

    if (j < NACTIONS) {
        float l = act_b[m * NACTIONS + j];
        #pragma unroll
        for (int s = 0; s < 16; s++) l += part[j * 16 + s];
        float mx = l;
        #pragma unroll
        for (int o = 8; o > 0; o >>= 1) mx = fmaxf(mx, __shfl_xor_sync(0x0000ffffu, mx, o, 16));
        float e = expf(l - mx);
        float ssum = e;
        #pragma unroll
        for (int o = 8; o > 0; o >>= 1) ssum += __shfl_xor_sync(0x0000ffffu, ssum, o, 16);
        out[OFF_ACT + (size_t)b * NACTIONS + j] = e / ssum;
    } else if (j == 16) {
        float v = base_b[m];
        #pragma unroll
        for (int w8 = 0; w8 < 8; w8++) v += bpart[w8];
        out[OFF_BASE + b] = v;
    }
}

// ---------------------------------------------------------------------------
// Kernel 2: comm_out = hid @ comm_w[m] + comm_b[m].
// 256 threads/block, 2 cols/thread (float2), n-specialized inner loops.
// ---------------------------------------------------------------------------
template <int R>
__device__ __forceinline__ void comm_body(const float2* __restrict__ w2,
                                          const float4 (*__restrict__ sh)[HIDSZ / 4],
                                          float2 bias, float2* acc) {
    #pragma unroll
    for (int r = 0; r < R; r++) acc[r] = bias;
    #pragma unroll 2
    for (int kq = 0; kq < HIDSZ / 4; kq++) {
        float2 w0 = w2[(size_t)(4 * kq + 0) * (COMM_OUT / 2)];
        float2 w1 = w2[(size_t)(4 * kq + 1) * (COMM_OUT / 2)];
        float2 w2v = w2[(size_t)(4 * kq + 2) * (COMM_OUT / 2)];
        float2 w3 = w2[(size_t)(4 * kq + 3) * (COMM_OUT / 2)];
        #pragma unroll
        for (int r = 0; r < R; r++) {
            float4 h = sh[r][kq];
            acc[r].x += h.x * w0.x + h.y * w1.x + h.z * w2v.x + h.w * w3.x;
            acc[r].y += h.x * w0.y + h.y * w1.y + h.z * w2v.y + h.w * w3.y;
        }
    }
}

__global__ void __launch_bounds__(256)
comm_kernel(const float* __restrict__ comm_w,
            const float* __restrict__ comm_b,
            float* __restrict__ out) {
    const int ci = blockIdx.x;
    if (ci >= g_nchunks) return;
    const int m = g_cm[ci];
    const int s = g_cs[ci];
    const int n = g_cn[ci];
    // col pair: 256 threads * 2 cols = 512 cols per block; grid.y = 4
    const int j = (blockIdx.y * 256 + threadIdx.x) * 2;

    __shared__ float4 sh[8][HIDSZ / 4];
    __shared__ int    rows[8];
    if (threadIdx.x < 8)
        rows[threadIdx.x] = (threadIdx.x < n) ? g_rows[s + threadIdx.x] : 0;
    __syncthreads();

    const float* hid = out + OFF_HID;
    for (int idx = threadIdx.x; idx < n * (HIDSZ / 4); idx += 256) {
        int r = idx >> 6, k = idx & 63;
        sh[r][k] = ((const float4*)(hid + (size_t)rows[r] * HIDSZ))[k];
    }
    __syncthreads();

    const float2 bias = *(const float2*)(comm_b + (size_t)m * COMM_OUT + j);
    const float2* w2 = (const float2*)(comm_w + (size_t)m * HIDSZ * COMM_OUT + j);

    float2 acc[8];
    if (n >= 7)      comm_body<8>(w2, sh, bias, acc);
    else if (n >= 5) comm_body<6>(w2, sh, bias, acc);
    else if (n >= 3) comm_body<4>(w2, sh, bias, acc);
    else if (n == 2) comm_body<2>(w2, sh, bias, acc);
    else             comm_body<1>(w2, sh, bias, acc);

    for (int r = 0; r < n; r++)
        *(float2*)(out + OFF_COMM + (size_t)rows[r] * COMM_OUT + j) = acc[r];
}

// ---------------------------------------------------------------------------
extern "C" void kernel_launch(void* const* d_in, const int* in_sizes, int n_in,
                              void* d_out, int out_size) {
    const float* inp      = (const float*)d_in[0];   // [256, 512]
    const float* prev_hid = (const float*)d_in[1];   // [256, 256]
    const float* comm_in  = (const float*)d_in[2];   // [256, 8, 256]
    const int*   ids      = (const int*)  d_in[3];   // [256]
    const float* enc_w    = (const float*)d_in[4];   // [512, 256]
    const float* enc_b    = (const float*)d_in[5];   // [256]
    const float* rnn_w    = (const float*)d_in[6];   // [64, 256, 256]
    const float* rnn_b    = (const float*)d_in[7];   // [64, 256]
    const float* act_w    = (const float*)d_in[8];   // [64, 256, 16]
    const float* act_b    = (const float*)d_in[9];   // [64, 16]
    const float* base_w   = (const float*)d_in[10];  // [64, 256, 1]
    const float* base_b   = (const float*)d_in[11];  // [64, 1]
    const float* comm_w   = (const float*)d_in[12];  // [64, 256, 2048]
    const float* comm_b   = (const float*)d_in[13];  // [64, 2048]
    float* out = (float*)d_out;

    group_kernel<<<1, BN>>>(ids);
    hid_act_kernel<<<BN, 256>>>(inp, prev_hid, comm_in, ids,
                                enc_w, enc_b, rnn_w, rnn_b,
                                act_w, act_b, base_w, base_b, out);
    comm_kernel<<<dim3(128, 4), 256>>>(comm_w, comm_b, out);
}

// round 4
// speedup vs baseline: 2.4656x; 1.1422x over previous
#include <cuda_runtime.h>

#define HIDSZ 256
#define NAGENTS 8
#define NMODELS 64
#define NACTIONS 16
#define BN 256
#define IN_DIM 512
#define COMM_OUT (HIDSZ * NAGENTS)   // 2048

// Output layout (concatenated in reference return order, fp32):
#define OFF_ACT  0
#define OFF_BASE (BN * NACTIONS)          // 4096
#define OFF_HID  (OFF_BASE + BN)          // 4352
#define OFF_COMM (OFF_HID + BN * HIDSZ)   // 69888

// ---------------- grouping scratch (device globals; no allocation) ----------
__device__ int g_rows[BN];      // row indices, sorted by model
__device__ int g_nchunks;
__device__ int g_cm[BN], g_cs[BN], g_cn[BN];   // chunk: model, start, count

// ---------------------------------------------------------------------------
// Grouping body: run by ONE extra block of hid_act_kernel (concurrent with
// the row blocks; must complete before comm_kernel, which launches after).
// ---------------------------------------------------------------------------
__device__ void group_body(const int* __restrict__ ids) {
    __shared__ int cnt[NMODELS];
    __shared__ int off[NMODELS];
    __shared__ int coff[NMODELS];
    __shared__ int cur[NMODELS];
    __shared__ int tmp[NMODELS];
    const int t = threadIdx.x;

    if (t < NMODELS) cnt[t] = 0;
    __syncthreads();
    const int m = ids[t];
    atomicAdd(&cnt[m], 1);
    __syncthreads();

    if (t < NMODELS) {
        off[t] = cnt[t];
        coff[t] = (cnt[t] + 7) >> 3;
    }
    __syncthreads();
    #pragma unroll
    for (int d = 1; d < NMODELS; d <<= 1) {
        int a = 0, b = 0;
        if (t < NMODELS && t >= d) { a = off[t - d]; b = coff[t - d]; }
        __syncthreads();
        if (t < NMODELS && t >= d) { off[t] += a; coff[t] += b; }
        __syncthreads();
    }
    if (t < NMODELS) {
        tmp[t] = off[t] - cnt[t];                 // exclusive row offset
        cur[t] = tmp[t];
        if (t == NMODELS - 1) g_nchunks = coff[t];
    }
    __syncthreads();
    if (t < NMODELS) {
        int co = coff[t] - ((cnt[t] + 7) >> 3);   // exclusive chunk offset
        int s = tmp[t], n = cnt[t];
        for (int c = 0; c < n; c += 8) {
            g_cm[co] = t;
            g_cs[co] = s + c;
            g_cn[co] = min(8, n - c);
            co++;
        }
    }
    __syncthreads();
    int pos = atomicAdd(&cur[m], 1);
    g_rows[pos] = t;
}

// ---------------------------------------------------------------------------
// Kernel 1 (fused): 2 rows per block. hid = relu(enc + rnn + comm_sum),
// then softmax(action) + baseline. Transposed dot: thread owns 4 output
// cols (float4 weight loads) and a k-slice; SMEM reduction of partials.
// Extra block (blockIdx.x == BN/2) does the model grouping.
// ---------------------------------------------------------------------------
__global__ void __launch_bounds__(256)
hid_act_kernel(const float* __restrict__ inp,
               const float* __restrict__ prev,
               const float* __restrict__ comm_in,
               const int*   __restrict__ ids,
               const float* __restrict__ enc_w,
               const float* __restrict__ enc_b,
               const float* __restrict__ rnn_w,
               const float* __restrict__ rnn_b,
               const float* __restrict__ act_w,
               const float* __restrict__ act_b,
               const float* __restrict__ base_w,
               const float* __restrict__ base_b,
               float* __restrict__ out) {
    if (blockIdx.x == BN / 2) { group_body(ids); return; }

    const int t  = threadIdx.x;
    const int b0 = blockIdx.x * 2;

    __shared__ float  sx[2][IN_DIM];      // 4 KB
    __shared__ float  sp[2][HIDSZ];       // 2 KB
    __shared__ float4 part[4][2][HIDSZ / 4];  // 8 KB
    __shared__ float  sh[2][HIDSZ];       // 2 KB
    __shared__ float  apart[2][NACTIONS][8];  // 1 KB
    __shared__ float  bres[2][4];
    __shared__ int    smid[2];

    // inp rows b0,b0+1 are contiguous: 1024 floats = 256 float4 (one/thread)
    ((float4*)sx)[t] = ((const float4*)(inp + (size_t)b0 * IN_DIM))[t];
    if (t < 128) ((float4*)sp)[t] = ((const float4*)(prev + (size_t)b0 * HIDSZ))[t];
    if (t < 2) smid[t] = ids[b0 + t];
    __syncthreads();
    const int m0 = smid[0], m1 = smid[1];

    const int jq = t & 63;   // output col quad: cols 4*jq .. 4*jq+3
    const int s  = t >> 6;   // k-slice 0..3

    float4 a0 = make_float4(0.f, 0.f, 0.f, 0.f);
    float4 a1 = make_float4(0.f, 0.f, 0.f, 0.f);

    // enc: k in [s*128, s*128+128)
    {
        const float4* w = (const float4*)enc_w + jq;
        #pragma unroll 4
        for (int k = s * 128; k < s * 128 + 128; k++) {
            float4 wv = w[k * 64];
            float x0 = sx[0][k], x1 = sx[1][k];
            a0.x += x0 * wv.x; a0.y += x0 * wv.y; a0.z += x0 * wv.z; a0.w += x0 * wv.w;
            a1.x += x1 * wv.x; a1.y += x1 * wv.y; a1.z += x1 * wv.z; a1.w += x1 * wv.w;
        }
    }
    // rnn: k in [s*64, s*64+64), separate weights per row (different models)
    {
        const float4* w0 = (const float4*)(rnn_w + (size_t)m0 * HIDSZ * HIDSZ) + jq;
        const float4* w1 = (const float4*)(rnn_w + (size_t)m1 * HIDSZ * HIDSZ) + jq;
        #pragma unroll 4
        for (int k = s * 64; k < s * 64 + 64; k++) {
            float4 wv0 = w0[k * 64];
            float4 wv1 = w1[k * 64];
            float p0 = sp[0][k], p1 = sp[1][k];
            a0.x += p0 * wv0.x; a0.y += p0 * wv0.y; a0.z += p0 * wv0.z; a0.w += p0 * wv0.w;
            a1.x += p1 * wv1.x; a1.y += p1 * wv1.y; a1.z += p1 * wv1.z; a1.w += p1 * wv1.w;
        }
    }
    part[s][0][jq] = a0;
    part[s][1][jq] = a1;
    __syncthreads();

    // finalize hid for 2 rows x 64 quads with 128 threads
    if (t < 128) {
        const int r = t >> 6, q = t & 63;
        const int mm = r ? m1 : m0;
        float4 v = part[0][r][q];
        float4 v1 = part[1][r][q], v2 = part[2][r][q], v3 = part[3][r][q];
        v.x += v1.x + v2.x + v3.x;
        v.y += v1.y + v2.y + v3.y;
        v.z += v1.z + v2.z + v3.z;
        v.w += v1.w + v2.w + v3.w;
        float4 eb = ((const float4*)enc_b)[q];
        float4 rb = ((const float4*)(rnn_b + (size_t)mm * HIDSZ))[q];
        float4 c = make_float4(0.f, 0.f, 0.f, 0.f);
        const float4* cb = (const float4*)(comm_in + (size_t)(b0 + r) * NAGENTS * HIDSZ) + q;
        #pragma unroll
        for (int a = 0; a < NAGENTS; a++) {
            float4 cv = cb[a * 64];
            c.x += cv.x; c.y += cv.y; c.z += cv.z; c.w += cv.w;
        }
        v.x = fmaxf(v.x + eb.x + rb.x + c.x, 0.f);
        v.y = fmaxf(v.y + eb.y + rb.y + c.y, 0.f);
        v.z = fmaxf(v.z + eb.z + rb.z + c.z, 0.f);
        v.w = fmaxf(v.w + eb.w + rb.w + c.w, 0.f);
        ((float4*)sh[r])[q] = v;
        ((float4*)(out + OFF_HID + (size_t)(b0 + r) * HIDSZ))[q] = v;
    }
    __syncthreads();

    // action partials: r = t>>7, within-row tt = t&127: o = tt&15, slice sl = tt>>4
    {
        const int r = t >> 7, tt = t & 127, o = tt & 15, sl = tt >> 4;
        const int mm = r ? m1 : m0;
        const float* aw = act_w + (size_t)mm * HIDSZ * NACTIONS + o;
        float p = 0.f;
        #pragma unroll 8
        for (int kk = 0; kk < 32; kk++) {
            int k = sl * 32 + kk;
            p += sh[r][k] * aw[(size_t)k * NACTIONS];
        }
        apart[r][o][sl] = p;
    }
    // baseline partials: 128 threads per row, 2 k's each, warp-reduced
    {
        const int r = t >> 7, tt = t & 127;
        const int mm = r ? m1 : m0;
        const float* bw = base_w + (size_t)mm * HIDSZ;
        float bp = sh[r][tt] * bw[tt] + sh[r][tt + 128] * bw[tt + 128];
        #pragma unroll
        for (int o = 16; o > 0; o >>= 1) bp += __shfl_xor_sync(0xffffffffu, bp, o);
        if ((t & 31) == 0) bres[r][(t >> 5) & 3] = bp;
    }
    __syncthreads();

    // final softmax (lanes 0-15 of warp 0 for row0, warp 4 for row1) + baseline
    {
        const int r = t >> 7, tt = t & 127;
        if (tt < NACTIONS) {
            const int mm = r ? m1 : m0;
            float l = act_b[mm * NACTIONS + tt];
            #pragma unroll
            for (int sl = 0; sl < 8; sl++) l += apart[r][tt][sl];
            float mx = l;
            #pragma unroll
            for (int o = 8; o > 0; o >>= 1) mx = fmaxf(mx, __shfl_xor_sync(0x0000ffffu, mx, o, 16));
            float e = expf(l - mx);
            float ssum = e;
            #pragma unroll
            for (int o = 8; o > 0; o >>= 1) ssum += __shfl_xor_sync(0x0000ffffu, ssum, o, 16);
            out[OFF_ACT + (size_t)(b0 + r) * NACTIONS + tt] = e / ssum;
        } else if (tt == 16) {
            const int mm = r ? m1 : m0;
            float v = base_b[mm] + bres[r][0] + bres[r][1] + bres[r][2] + bres[r][3];
            out[OFF_BASE + b0 + r] = v;
        }
    }
}

// ---------------------------------------------------------------------------
// Kernel 2: comm_out = hid @ comm_w[m] + comm_b[m].
// 256 threads/block, 2 cols/thread (float2), exact-R inner loops.
// ---------------------------------------------------------------------------
template <int R>
__device__ __forceinline__ void comm_body(const float2* __restrict__ w2,
                                          const float4 (*__restrict__ sh)[HIDSZ / 4],
                                          float2 bias, float2* acc) {
    #pragma unroll
    for (int r = 0; r < R; r++) acc[r] = bias;
    #pragma unroll 2
    for (int kq = 0; kq < HIDSZ / 4; kq++) {
        float2 w0 = w2[(size_t)(4 * kq + 0) * (COMM_OUT / 2)];
        float2 w1 = w2[(size_t)(4 * kq + 1) * (COMM_OUT / 2)];
        float2 wv2 = w2[(size_t)(4 * kq + 2) * (COMM_OUT / 2)];
        float2 w3 = w2[(size_t)(4 * kq + 3) * (COMM_OUT / 2)];
        #pragma unroll
        for (int r = 0; r < R; r++) {
            float4 h = sh[r][kq];
            acc[r].x += h.x * w0.x + h.y * w1.x + h.z * wv2.x + h.w * w3.x;
            acc[r].y += h.x * w0.y + h.y * w1.y + h.z * wv2.y + h.w * w3.y;
        }
    }
}

__global__ void __launch_bounds__(256)
comm_kernel(const float* __restrict__ comm_w,
            const float* __restrict__ comm_b,
            float* __restrict__ out) {
    const int ci = blockIdx.x;
    if (ci >= g_nchunks) return;
    const int m = g_cm[ci];
    const int s = g_cs[ci];
    const int n = g_cn[ci];
    const int j = (blockIdx.y * 256 + threadIdx.x) * 2;

    __shared__ float4 sh[8][HIDSZ / 4];
    __shared__ int    rows[8];
    if (threadIdx.x < 8)
        rows[threadIdx.x] = (threadIdx.x < n) ? g_rows[s + threadIdx.x] : 0;
    __syncthreads();

    const float* hid = out + OFF_HID;
    for (int idx = threadIdx.x; idx < n * (HIDSZ / 4); idx += 256) {
        int r = idx >> 6, k = idx & 63;
        sh[r][k] = ((const float4*)(hid + (size_t)rows[r] * HIDSZ))[k];
    }
    __syncthreads();

    const float2 bias = *(const float2*)(comm_b + (size_t)m * COMM_OUT + j);
    const float2* w2 = (const float2*)(comm_w + (size_t)m * HIDSZ * COMM_OUT + j);

    float2 acc[8];
    switch (n) {
        case 8: comm_body<8>(w2, sh, bias, acc); break;
        case 7: comm_body<7>(w2, sh, bias, acc); break;
        case 6: comm_body<6>(w2, sh, bias, acc); break;
        case 5: comm_body<5>(w2, sh, bias, acc); break;
        case 4: comm_body<4>(w2, sh, bias, acc); break;
        case 3: comm_body<3>(w2, sh, bias, acc); break;
        case 2: comm_body<2>(w2, sh, bias, acc); break;
        default: comm_body<1>(w2, sh, bias, acc); break;
    }

    for (int r = 0; r < n; r++)
        *(float2*)(out + OFF_COMM + (size_t)rows[r] * COMM_OUT + j) = acc[r];
}

// ---------------------------------------------------------------------------
extern "C" void kernel_launch(void* const* d_in, const int* in_sizes, int n_in,
                              void* d_out, int out_size) {
    const float* inp      = (const float*)d_in[0];   // [256, 512]
    const float* prev_hid = (const float*)d_in[1];   // [256, 256]
    const float* comm_in  = (const float*)d_in[2];   // [256, 8, 256]
    const int*   ids      = (const int*)  d_in[3];   // [256]
    const float* enc_w    = (const float*)d_in[4];   // [512, 256]
    const float* enc_b    = (const float*)d_in[5];   // [256]
    const float* rnn_w    = (const float*)d_in[6];   // [64, 256, 256]
    const float* rnn_b    = (const float*)d_in[7];   // [64, 256]
    const float* act_w    = (const float*)d_in[8];   // [64, 256, 16]
    const float* act_b    = (const float*)d_in[9];   // [64, 16]
    const float* base_w   = (const float*)d_in[10];  // [64, 256, 1]
    const float* base_b   = (const float*)d_in[11];  // [64, 1]
    const float* comm_w   = (const float*)d_in[12];  // [64, 256, 2048]
    const float* comm_b   = (const float*)d_in[13];  // [64, 2048]
    float* out = (float*)d_out;

    hid_act_kernel<<<BN / 2 + 1, 256>>>(inp, prev_hid, comm_in, ids,
                                        enc_w, enc_b, rnn_w, rnn_b,
                                        act_w, act_b, base_w, base_b, out);
    comm_kernel<<<dim3(128, 4), 256>>>(comm_w, comm_b, out);
}